// round 5
// baseline (speedup 1.0000x reference)
#include <cuda_runtime.h>

#define FULL 0xffffffffu

// Scratch (static device globals — allocation-free).
__device__ float g_partial[2][64][4096];   // per-(group,b,l) head-reduction partials
__device__ float g_S[3][64][128];          // per-quarter dot partials S_q[b][i]

__device__ __forceinline__ float tanh_approx(float v) {
    float r;
    asm("tanh.approx.f32 %0, %1;" : "=f"(r) : "f"(v));
    return r;
}

// ---------------------------------------------------------------------------
// K0: quarter partial dots  S_q[b][i] = sum_{j in quarter q} W1[i,j]*x[b,j]
// grid (16 batch-quads, 4 head-chunks of 32, 3 quarters) = 192 blocks, 256 thr.
// Small blocks, low regs -> several blocks/SM, all SMs busy. W1 traffic 24 MB.
// ---------------------------------------------------------------------------
__global__ __launch_bounds__(256, 4)
void nade_carry_kernel(const float* __restrict__ x,
                       const float* __restrict__ W1)
{
    __shared__ float xs[4 * 1024];             // 16 KB: 4 batch quarter-rows

    const int bq   = blockIdx.x;               // batch quad
    const int hg   = blockIdx.y;               // head chunk (32 heads)
    const int q    = blockIdx.z;               // quarter 0..2
    const int tid  = threadIdx.x;
    const int w    = tid >> 5;                 // 8 warps
    const int lane = tid & 31;

    const float4* x4  = reinterpret_cast<const float4*>(x);
    float4*       xs4 = reinterpret_cast<float4*>(xs);
    for (int idx = tid; idx < 1024; idx += 256) {
        const int nb = idx >> 8;
        const int r  = idx & 255;
        xs4[idx] = x4[(bq * 4 + nb) * 1024 + q * 256 + r];
    }
    __syncthreads();

    const float4* W1_4 = reinterpret_cast<const float4*>(W1);

    // Warp owns 4 heads.
    #pragma unroll
    for (int h = 0; h < 4; h++) {
        const int i = hg * 32 + w * 4 + h;
        float acc0 = 0.f, acc1 = 0.f, acc2 = 0.f, acc3 = 0.f;
        #pragma unroll
        for (int c = 0; c < 8; c++) {
            const int j4 = c * 32 + lane;
            const float4 w1v = W1_4[i * 1024 + q * 256 + j4];
            const float4 x0 = xs4[0 * 256 + j4];
            const float4 x1 = xs4[1 * 256 + j4];
            const float4 x2 = xs4[2 * 256 + j4];
            const float4 x3 = xs4[3 * 256 + j4];
            acc0 = fmaf(x0.x, w1v.x, fmaf(x0.y, w1v.y, fmaf(x0.z, w1v.z, fmaf(x0.w, w1v.w, acc0))));
            acc1 = fmaf(x1.x, w1v.x, fmaf(x1.y, w1v.y, fmaf(x1.z, w1v.z, fmaf(x1.w, w1v.w, acc1))));
            acc2 = fmaf(x2.x, w1v.x, fmaf(x2.y, w1v.y, fmaf(x2.z, w1v.z, fmaf(x2.w, w1v.w, acc2))));
            acc3 = fmaf(x3.x, w1v.x, fmaf(x3.y, w1v.y, fmaf(x3.z, w1v.z, fmaf(x3.w, w1v.w, acc3))));
        }
        float a[4] = {acc0, acc1, acc2, acc3};
        #pragma unroll
        for (int o = 16; o > 0; o >>= 1) {
            a[0] += __shfl_down_sync(FULL, a[0], o);
            a[1] += __shfl_down_sync(FULL, a[1], o);
            a[2] += __shfl_down_sync(FULL, a[2], o);
            a[3] += __shfl_down_sync(FULL, a[3], o);
        }
        if (lane == 0) {
            #pragma unroll
            for (int nb = 0; nb < 4; nb++)
                g_S[q][bq * 4 + nb][i] = a[nb];
        }
    }
}

// ---------------------------------------------------------------------------
// K1: scan + sigmoid + head reduction. 4 batches/block, quarter of j.
// grid (16 batch-quads, 2 head-groups, 4 j-quarters) = 128 blocks, 512 thr.
// Batch-scans run level-by-level together: 4 concurrent SHFL chains.
// ---------------------------------------------------------------------------
__global__ __launch_bounds__(512, 1)
void nade_main_kernel(const float* __restrict__ x,
                      const float* __restrict__ W1,
                      const float* __restrict__ b1,
                      const float* __restrict__ W2)
{
    __shared__ float xs[4 * 1024];             // 16 KB
    __shared__ float red[16][4][128];          // 32 KB

    const int b0   = blockIdx.x * 4;
    const int g    = blockIdx.y;
    const int q    = blockIdx.z;
    const int tid  = threadIdx.x;
    const int w    = tid >> 5;
    const int lane = tid & 31;

    const float4* x4  = reinterpret_cast<const float4*>(x);
    float4*       xs4 = reinterpret_cast<float4*>(xs);
    for (int idx = tid; idx < 1024; idx += 512) {
        const int nb = idx >> 8;
        const int r  = idx & 255;
        xs4[idx] = x4[(b0 + nb) * 1024 + q * 256 + r];
    }
    __syncthreads();

    const int i0 = g * 64 + w * 4;

    // cb[h][nb] = 0.5 * (b1[i] + carry from previous quarters + running prefix)
    float cb[16];
    #pragma unroll
    for (int h = 0; h < 4; h++) {
        const float base = b1[i0 + h];
        #pragma unroll
        for (int nb = 0; nb < 4; nb++) {
            float c = base;
            for (int qq = 0; qq < q; qq++) c += g_S[qq][b0 + nb][i0 + h];
            cb[h * 4 + nb] = 0.5f * c;
        }
    }

    const float4* W1_4 = reinterpret_cast<const float4*>(W1);
    const float4* W2_4 = reinterpret_cast<const float4*>(W2);

    for (int t = 0; t < 8; ++t) {
        const int j0 = t * 128;                // within quarter
        const int jv = t * 32 + lane;          // float4 idx within quarter

        float4 xv[4];
        #pragma unroll
        for (int nb = 0; nb < 4; nb++) xv[nb] = xs4[nb * 256 + jv];

        float4 acc[4];
        #pragma unroll
        for (int nb = 0; nb < 4; nb++) acc[nb] = make_float4(0.f, 0.f, 0.f, 0.f);

        #pragma unroll
        for (int h = 0; h < 4; h++) {
            const int i = i0 + h;
            const float4 w1v = W1_4[i * 1024 + q * 256 + jv];
            const float4 w2v = W2_4[i * 1024 + q * 256 + jv];

            // Per-lane inclusive partials for all 4 batches first.
            float s0[4], s1[4], s2[4], inc[4], lt[4];
            #pragma unroll
            for (int nb = 0; nb < 4; nb++) {
                s0[nb] = xv[nb].x * w1v.x;
                s1[nb] = fmaf(xv[nb].y, w1v.y, s0[nb]);
                s2[nb] = fmaf(xv[nb].z, w1v.z, s1[nb]);
                lt[nb] = fmaf(xv[nb].w, w1v.w, s2[nb]);   // lane total
                inc[nb] = lt[nb];
            }

            // Batched warp scan: 4 concurrent shuffle chains per level.
            #pragma unroll
            for (int o = 1; o < 32; o <<= 1) {
                const float v0 = __shfl_up_sync(FULL, inc[0], o);
                const float v1 = __shfl_up_sync(FULL, inc[1], o);
                const float v2 = __shfl_up_sync(FULL, inc[2], o);
                const float v3 = __shfl_up_sync(FULL, inc[3], o);
                if (lane >= o) {
                    inc[0] += v0; inc[1] += v1; inc[2] += v2; inc[3] += v3;
                }
            }

            // Batched broadcast of tile totals.
            float tot[4];
            #pragma unroll
            for (int nb = 0; nb < 4; nb++)
                tot[nb] = __shfl_sync(FULL, inc[nb], 31);

            #pragma unroll
            for (int nb = 0; nb < 4; nb++) {
                const float base = inc[nb] - lt[nb];     // exclusive lane base
                const float c2l = fmaf(0.5f, base, cb[h * 4 + nb]);
                const float a0 = c2l;
                const float a1 = fmaf(0.5f, s0[nb], c2l);
                const float a2 = fmaf(0.5f, s1[nb], c2l);
                const float a3 = fmaf(0.5f, s2[nb], c2l);

                const float t0 = tanh_approx(a0);
                const float t1 = tanh_approx(a1);
                const float t2 = tanh_approx(a2);
                const float t3 = tanh_approx(a3);

                acc[nb].x = fmaf(fmaf(0.5f, t0, 0.5f), w2v.x, acc[nb].x);
                acc[nb].y = fmaf(fmaf(0.5f, t1, 0.5f), w2v.y, acc[nb].y);
                acc[nb].z = fmaf(fmaf(0.5f, t2, 0.5f), w2v.z, acc[nb].z);
                acc[nb].w = fmaf(fmaf(0.5f, t3, 0.5f), w2v.w, acc[nb].w);

                cb[h * 4 + nb] = fmaf(0.5f, tot[nb], cb[h * 4 + nb]);
            }
        }

        // Stage partials: warp w, batch nb, 128 l values.
        #pragma unroll
        for (int nb = 0; nb < 4; nb++)
            reinterpret_cast<float4*>(&red[w][nb][0])[lane] = acc[nb];
        __syncthreads();

        // All 16 warps reduce: warp -> (batch w>>2, l-chunk w&3).
        {
            const int nbr = w >> 2;
            const int l   = (w & 3) * 32 + lane;
            float sum = 0.f;
            #pragma unroll
            for (int ww = 0; ww < 16; ++ww) sum += red[ww][nbr][l];
            g_partial[g][b0 + nbr][q * 1024 + j0 + l] = sum;
        }
        __syncthreads();
    }
}

// ---------------------------------------------------------------------------
// K2: combine group partials + b2, accurate final sigmoid.
// 2 float4 per thread for MLP=6.
// ---------------------------------------------------------------------------
__global__ __launch_bounds__(256)
void nade_final_kernel(const float* __restrict__ b2,
                       float* __restrict__ out)
{
    const int tid  = blockIdx.x * blockDim.x + threadIdx.x;  // 0..32767
    const int idxA = tid * 2;
    const int idxB = tid * 2 + 1;

    const int bA = idxA >> 10, rA = idxA & 1023;
    const int bB = idxB >> 10, rB = idxB & 1023;

    const float4 p0A = reinterpret_cast<const float4*>(&g_partial[0][bA][0])[rA];
    const float4 p1A = reinterpret_cast<const float4*>(&g_partial[1][bA][0])[rA];
    const float4 p0B = reinterpret_cast<const float4*>(&g_partial[0][bB][0])[rB];
    const float4 p1B = reinterpret_cast<const float4*>(&g_partial[1][bB][0])[rB];
    const float4 bvA = reinterpret_cast<const float4*>(b2)[rA];
    const float4 bvB = reinterpret_cast<const float4*>(b2)[rB];

    float4 oA, oB;
    oA.x = 1.0f / (1.0f + __expf(-(p0A.x + p1A.x + bvA.x)));
    oA.y = 1.0f / (1.0f + __expf(-(p0A.y + p1A.y + bvA.y)));
    oA.z = 1.0f / (1.0f + __expf(-(p0A.z + p1A.z + bvA.z)));
    oA.w = 1.0f / (1.0f + __expf(-(p0A.w + p1A.w + bvA.w)));
    oB.x = 1.0f / (1.0f + __expf(-(p0B.x + p1B.x + bvB.x)));
    oB.y = 1.0f / (1.0f + __expf(-(p0B.y + p1B.y + bvB.y)));
    oB.z = 1.0f / (1.0f + __expf(-(p0B.z + p1B.z + bvB.z)));
    oB.w = 1.0f / (1.0f + __expf(-(p0B.w + p1B.w + bvB.w)));

    reinterpret_cast<float4*>(out)[idxA] = oA;
    reinterpret_cast<float4*>(out)[idxB] = oB;
}

extern "C" void kernel_launch(void* const* d_in, const int* in_sizes, int n_in,
                              void* d_out, int out_size)
{
    const float* x  = (const float*)d_in[0];
    const float* W1 = (const float*)d_in[1];
    const float* b1 = (const float*)d_in[2];
    const float* W2 = (const float*)d_in[3];
    const float* b2 = (const float*)d_in[4];

    nade_carry_kernel<<<dim3(16, 4, 3), 256>>>(x, W1);
    nade_main_kernel<<<dim3(16, 2, 4), 512>>>(x, W1, b1, W2);
    nade_final_kernel<<<128, 256>>>(b2, (float*)d_out);
}

// round 8
// speedup vs baseline: 1.2220x; 1.2220x over previous
#include <cuda_runtime.h>

#define FULL 0xffffffffu

// Scratch (static device globals — allocation-free).
__device__ float g_partial[4][64][4096];   // per-(head-group,b,l) partials (4 MB)
__device__ float g_S[3][64][128];          // per-quarter dot partials S_q[b][i]

__device__ __forceinline__ float tanh_approx(float v) {
    float r;
    asm("tanh.approx.f32 %0, %1;" : "=f"(r) : "f"(v));
    return r;
}

// ---------------------------------------------------------------------------
// K0: quarter partial dots  S_q[b][i] = sum_{j in quarter q} W1[i,j]*x[b,j]
// grid (8 batch-octets, 16 head-chunks of 8, 3 quarters) = 384 blocks, 128 thr.
// No smem, no reg cap. Warp owns 2 heads x 8 batches; x float4s hoisted into
// registers per c-step and reused across both heads (16 independent FMA chains).
// ---------------------------------------------------------------------------
__global__ __launch_bounds__(128)
void nade_carry_kernel(const float* __restrict__ x,
                       const float* __restrict__ W1)
{
    const int bo   = blockIdx.x;               // batch octet
    const int hg   = blockIdx.y;               // head chunk (8 heads)
    const int q    = blockIdx.z;               // quarter 0..2
    const int tid  = threadIdx.x;
    const int w    = tid >> 5;                 // 4 warps
    const int lane = tid & 31;

    const float4* x4   = reinterpret_cast<const float4*>(x);
    const float4* W1_4 = reinterpret_cast<const float4*>(W1);

    const int i0 = hg * 8 + w * 2;             // first of 2 heads for this warp

    float acc[2][8];
    #pragma unroll
    for (int h = 0; h < 2; h++)
        #pragma unroll
        for (int nb = 0; nb < 8; nb++) acc[h][nb] = 0.f;

    #pragma unroll 2
    for (int c = 0; c < 8; c++) {
        const int j4 = q * 256 + c * 32 + lane;    // float4 idx in row

        float4 xv[8];
        #pragma unroll
        for (int nb = 0; nb < 8; nb++)
            xv[nb] = x4[(bo * 8 + nb) * 1024 + j4];

        #pragma unroll
        for (int h = 0; h < 2; h++) {
            const float4 w1v = W1_4[(i0 + h) * 1024 + j4];
            #pragma unroll
            for (int nb = 0; nb < 8; nb++) {
                acc[h][nb] = fmaf(xv[nb].x, w1v.x,
                             fmaf(xv[nb].y, w1v.y,
                             fmaf(xv[nb].z, w1v.z,
                             fmaf(xv[nb].w, w1v.w, acc[h][nb]))));
            }
        }
    }

    // Butterfly reduce all 16 accumulators (level-batched for overlap).
    #pragma unroll
    for (int o = 16; o > 0; o >>= 1) {
        #pragma unroll
        for (int h = 0; h < 2; h++)
            #pragma unroll
            for (int nb = 0; nb < 8; nb++)
                acc[h][nb] += __shfl_down_sync(FULL, acc[h][nb], o);
    }
    if (lane == 0) {
        #pragma unroll
        for (int h = 0; h < 2; h++)
            #pragma unroll
            for (int nb = 0; nb < 8; nb++)
                g_S[q][bo * 8 + nb][i0 + h] = acc[h][nb];
    }
}

// ---------------------------------------------------------------------------
// K1: scan + sigmoid + head reduction. 4 batches/block, 32 heads/block,
// quarter of j. grid (16 bq, 4 head-groups, 4 quarters) = 256 blocks, 256 thr,
// ~2 blocks/SM so barrier & scan latency overlaps across blocks.
// Warp owns 4 heads x 4 batches; batched 4-chain warp scan.
// ---------------------------------------------------------------------------
__global__ __launch_bounds__(256, 2)
void nade_main_kernel(const float* __restrict__ x,
                      const float* __restrict__ W1,
                      const float* __restrict__ b1,
                      const float* __restrict__ W2)
{
    __shared__ float xs[4 * 1024];             // 16 KB: 4 batch quarter-rows
    __shared__ float red[8][4][128];           // 16 KB: warp partials

    const int b0   = blockIdx.x * 4;
    const int g    = blockIdx.y;               // head group of 32
    const int q    = blockIdx.z;
    const int tid  = threadIdx.x;
    const int w    = tid >> 5;                 // 8 warps
    const int lane = tid & 31;

    const float4* x4  = reinterpret_cast<const float4*>(x);
    float4*       xs4 = reinterpret_cast<float4*>(xs);
    for (int idx = tid; idx < 1024; idx += 256) {
        const int nb = idx >> 8;
        const int r  = idx & 255;
        xs4[idx] = x4[(b0 + nb) * 1024 + q * 256 + r];
    }
    __syncthreads();

    const int i0 = g * 32 + w * 4;

    // cb[h][nb] = 0.5 * (b1[i] + carry from previous quarters + running prefix)
    float cb[16];
    #pragma unroll
    for (int h = 0; h < 4; h++) {
        const float base = b1[i0 + h];
        #pragma unroll
        for (int nb = 0; nb < 4; nb++) {
            float c = base;
            for (int qq = 0; qq < q; qq++) c += g_S[qq][b0 + nb][i0 + h];
            cb[h * 4 + nb] = 0.5f * c;
        }
    }

    const float4* W1_4 = reinterpret_cast<const float4*>(W1);
    const float4* W2_4 = reinterpret_cast<const float4*>(W2);

    for (int t = 0; t < 8; ++t) {
        const int j0 = t * 128;                // within quarter
        const int jv = t * 32 + lane;          // float4 idx within quarter

        float4 xv[4];
        #pragma unroll
        for (int nb = 0; nb < 4; nb++) xv[nb] = xs4[nb * 256 + jv];

        float4 acc[4];
        #pragma unroll
        for (int nb = 0; nb < 4; nb++) acc[nb] = make_float4(0.f, 0.f, 0.f, 0.f);

        #pragma unroll
        for (int h = 0; h < 4; h++) {
            const int i = i0 + h;
            const float4 w1v = W1_4[i * 1024 + q * 256 + jv];
            const float4 w2v = W2_4[i * 1024 + q * 256 + jv];

            // Per-lane inclusive partials for all 4 batches first.
            float s0[4], s1[4], s2[4], inc[4], lt[4];
            #pragma unroll
            for (int nb = 0; nb < 4; nb++) {
                s0[nb] = xv[nb].x * w1v.x;
                s1[nb] = fmaf(xv[nb].y, w1v.y, s0[nb]);
                s2[nb] = fmaf(xv[nb].z, w1v.z, s1[nb]);
                lt[nb] = fmaf(xv[nb].w, w1v.w, s2[nb]);   // lane total
                inc[nb] = lt[nb];
            }

            // Batched warp scan: 4 concurrent shuffle chains per level.
            #pragma unroll
            for (int o = 1; o < 32; o <<= 1) {
                const float v0 = __shfl_up_sync(FULL, inc[0], o);
                const float v1 = __shfl_up_sync(FULL, inc[1], o);
                const float v2 = __shfl_up_sync(FULL, inc[2], o);
                const float v3 = __shfl_up_sync(FULL, inc[3], o);
                if (lane >= o) {
                    inc[0] += v0; inc[1] += v1; inc[2] += v2; inc[3] += v3;
                }
            }

            float tot[4];
            #pragma unroll
            for (int nb = 0; nb < 4; nb++)
                tot[nb] = __shfl_sync(FULL, inc[nb], 31);

            #pragma unroll
            for (int nb = 0; nb < 4; nb++) {
                const float base = inc[nb] - lt[nb];     // exclusive lane base
                const float c2l = fmaf(0.5f, base, cb[h * 4 + nb]);
                const float a0 = c2l;
                const float a1 = fmaf(0.5f, s0[nb], c2l);
                const float a2 = fmaf(0.5f, s1[nb], c2l);
                const float a3 = fmaf(0.5f, s2[nb], c2l);

                const float t0 = tanh_approx(a0);
                const float t1 = tanh_approx(a1);
                const float t2 = tanh_approx(a2);
                const float t3 = tanh_approx(a3);

                acc[nb].x = fmaf(fmaf(0.5f, t0, 0.5f), w2v.x, acc[nb].x);
                acc[nb].y = fmaf(fmaf(0.5f, t1, 0.5f), w2v.y, acc[nb].y);
                acc[nb].z = fmaf(fmaf(0.5f, t2, 0.5f), w2v.z, acc[nb].z);
                acc[nb].w = fmaf(fmaf(0.5f, t3, 0.5f), w2v.w, acc[nb].w);

                cb[h * 4 + nb] = fmaf(0.5f, tot[nb], cb[h * 4 + nb]);
            }
        }

        // Stage partials: warp w, batch nb, 128 l values.
        #pragma unroll
        for (int nb = 0; nb < 4; nb++)
            reinterpret_cast<float4*>(&red[w][nb][0])[lane] = acc[nb];
        __syncthreads();

        // 8 warps reduce 512 outputs: warp -> (batch w>>1, l-half w&1), 2 l/lane.
        {
            const int nbr = w >> 1;
            const int l0  = (w & 1) * 64 + lane;
            float sumA = 0.f, sumB = 0.f;
            #pragma unroll
            for (int ww = 0; ww < 8; ++ww) {
                sumA += red[ww][nbr][l0];
                sumB += red[ww][nbr][l0 + 32];
            }
            g_partial[g][b0 + nbr][q * 1024 + j0 + l0]      = sumA;
            g_partial[g][b0 + nbr][q * 1024 + j0 + l0 + 32] = sumB;
        }
        __syncthreads();
    }
}

// ---------------------------------------------------------------------------
// K2: combine 4 group partials + b2, accurate final sigmoid (float4/thread).
// ---------------------------------------------------------------------------
__global__ __launch_bounds__(256)
void nade_final_kernel(const float* __restrict__ b2,
                       float* __restrict__ out)
{
    const int idx4 = blockIdx.x * blockDim.x + threadIdx.x;  // 0..65535
    const int b = idx4 >> 10;
    const int r = idx4 & 1023;
    const float4 p0 = reinterpret_cast<const float4*>(&g_partial[0][b][0])[r];
    const float4 p1 = reinterpret_cast<const float4*>(&g_partial[1][b][0])[r];
    const float4 p2 = reinterpret_cast<const float4*>(&g_partial[2][b][0])[r];
    const float4 p3 = reinterpret_cast<const float4*>(&g_partial[3][b][0])[r];
    const float4 bv = reinterpret_cast<const float4*>(b2)[r];
    float4 o;
    o.x = 1.0f / (1.0f + __expf(-((p0.x + p1.x) + (p2.x + p3.x) + bv.x)));
    o.y = 1.0f / (1.0f + __expf(-((p0.y + p1.y) + (p2.y + p3.y) + bv.y)));
    o.z = 1.0f / (1.0f + __expf(-((p0.z + p1.z) + (p2.z + p3.z) + bv.z)));
    o.w = 1.0f / (1.0f + __expf(-((p0.w + p1.w) + (p2.w + p3.w) + bv.w)));
    reinterpret_cast<float4*>(out)[idx4] = o;
}

extern "C" void kernel_launch(void* const* d_in, const int* in_sizes, int n_in,
                              void* d_out, int out_size)
{
    const float* x  = (const float*)d_in[0];
    const float* W1 = (const float*)d_in[1];
    const float* b1 = (const float*)d_in[2];
    const float* W2 = (const float*)d_in[3];
    const float* b2 = (const float*)d_in[4];

    nade_carry_kernel<<<dim3(8, 16, 3), 128>>>(x, W1);
    nade_main_kernel<<<dim3(16, 4, 4), 256>>>(x, W1, b1, W2);
    nade_final_kernel<<<256, 256>>>(b2, (float*)d_out);
}